// round 1
// baseline (speedup 1.0000x reference)
#include <cuda_runtime.h>
#include <cuda_bf16.h>

// ---------------------------------------------------------------------------
// Strategy:
//  * Gamma(c, lam) depends only on (c, lam) through a small shared MLP.
//    Precompute per-lambda-row Chebyshev coefficients (degree 23) of Gamma
//    over c in [-1, 2]; main kernel does lambda-lerp of coefficients once,
//    then every Gamma eval is a pure-FMA Clenshaw recurrence (no loads, no MUFU).
//  * A (spectral amplitude) never feeds back into (c, v), so the flow MLP is
//    dead code during the 10 shooting iterations -> only evaluated in the
//    final integrate (10 evals/element).
//  * tanh for the flow MLP: rational minimax (Eigen coefficients) with a
//    bit-hack Newton reciprocal -> zero MUFU in the hot path.
// ---------------------------------------------------------------------------

#define NC      24          // Chebyshev terms (degree 23)
#define NCPAD   32          // padded row stride (128B-aligned rows)
#define GL      2048        // lambda grid rows
#define C_MIN   (-1.0f)
#define C_MAX   (2.0f)
#define C_MID   (0.5f)
#define C_HALF  (1.5f)
#define C_INVH  (0.66666666666666667f)
#define PI_F    3.14159265358979323846f
#define FD_EPS_F 1e-4f

__device__ float g_nodes[GL * NC];     // Gamma sampled at Chebyshev nodes
__device__ float g_coef [GL * NCPAD];  // Chebyshev coefficients per lambda row

// ----------------------------- precompute ----------------------------------

__device__ __forceinline__ float softplus_ref(float x) {
    return (x > 20.0f) ? x : log1pf(expf(x));
}

__device__ __forceinline__ float metric_eval(
    float c, float lam,
    const float* __restrict__ mW1, const float* __restrict__ mb1,
    const float* __restrict__ mW2, const float* __restrict__ mb2,
    const float* __restrict__ mW3, const float* __restrict__ mb3)
{
    float h1[8];
#pragma unroll
    for (int j = 0; j < 8; j++) {
        float p = fmaf(c, mW1[j], fmaf(lam, mW1[8 + j], mb1[j]));
        h1[j] = tanhf(p);
    }
    float h2[8];
#pragma unroll
    for (int j = 0; j < 8; j++) {
        float p = mb2[j];
#pragma unroll
        for (int k = 0; k < 8; k++) p = fmaf(h1[k], mW2[k * 8 + j], p);
        h2[j] = tanhf(p);
    }
    float o = mb3[0];
#pragma unroll
    for (int k = 0; k < 8; k++) o = fmaf(h2[k], mW3[k], o);
    return softplus_ref(o) + 1e-6f;
}

__global__ void gamma_nodes_kernel(
    const float* __restrict__ mW1, const float* __restrict__ mb1,
    const float* __restrict__ mW2, const float* __restrict__ mb2,
    const float* __restrict__ mW3, const float* __restrict__ mb3)
{
    int id = blockIdx.x * blockDim.x + threadIdx.x;
    if (id >= GL * NC) return;
    int l = id / NC;
    int k = id - l * NC;
    float lam = (float)l * (1.0f / (GL - 1));
    float th = (k + 0.5f) * (PI_F / NC);
    float c  = C_MID + C_HALF * cosf(th);

    float g0 = metric_eval(c,            lam, mW1, mb1, mW2, mb2, mW3, mb3);
    float gp = metric_eval(c + FD_EPS_F, lam, mW1, mb1, mW2, mb2, mW3, mb3);
    float gm = metric_eval(c - FD_EPS_F, lam, mW1, mb1, mW2, mb2, mW3, mb3);
    float dg = (gp - gm) * (1.0f / (2.0f * FD_EPS_F));
    g_nodes[id] = 0.5f * dg / g0;
}

__global__ void dct_kernel()
{
    int id = blockIdx.x * blockDim.x + threadIdx.x;
    if (id >= GL * NC) return;
    int l = id / NC;
    int j = id - l * NC;
    float s = 0.0f;
    for (int k = 0; k < NC; k++) {
        s += g_nodes[l * NC + k] * cosf((PI_F / NC) * (float)j * ((float)k + 0.5f));
    }
    s *= (j == 0) ? (1.0f / NC) : (2.0f / NC);   // a0 stored pre-halved
    g_coef[l * NCPAD + j] = s;
}

// ----------------------------- main kernel ---------------------------------

__device__ __forceinline__ float fast_rcp(float q) {
    // bit-hack initial guess + 2 Newton iterations (rel err ~7e-6), 0 MUFU
    float r = __uint_as_float(0x7EF311C3u - __float_as_uint(q));
    r = r * (2.0f - q * r);
    r = r * (2.0f - q * r);
    return r;
}

__device__ __forceinline__ float tanh_fast(float x) {
    // Eigen-style rational minimax tanh, |err| < ~1e-6, FMA-only
    float xc = fminf(fmaxf(x, -7.90531110763549805f), 7.90531110763549805f);
    float x2 = xc * xc;
    float p = fmaf(x2, -2.76076847742355e-16f, 2.00018790482477e-13f);
    p = fmaf(x2, p, -8.60467152213735e-11f);
    p = fmaf(x2, p,  5.12229709037114e-08f);
    p = fmaf(x2, p,  1.48572235717979e-05f);
    p = fmaf(x2, p,  6.37261928875436e-04f);
    p = fmaf(x2, p,  4.89352455891786e-03f);
    p *= xc;
    float q = fmaf(x2, 1.19825839466702e-06f, 1.18534705686654e-04f);
    q = fmaf(x2, q, 2.26843463243900e-03f);
    q = fmaf(x2, q, 4.89352518554385e-03f);
    return p * fast_rcp(q);
}

__device__ __forceinline__ float eval_gamma(const float co[NC], float c) {
    float cc = fminf(fmaxf(c, C_MIN), C_MAX);
    float t  = (cc - C_MID) * C_INVH;
    float t2 = t + t;
    float b1 = 0.0f, b2 = 0.0f;
#pragma unroll
    for (int j = NC - 1; j >= 1; j--) {
        float b = fmaf(t2, b1, co[j] - b2);
        b2 = b1;
        b1 = b;
    }
    return fmaf(t, b1, co[0] - b2);
}

__global__ __launch_bounds__(256)
void geodesic_main_kernel(
    const float* __restrict__ c_src, const float* __restrict__ c_tgt,
    const float* __restrict__ lamv,  const float* __restrict__ A_src,
    const float* __restrict__ sW1,   const float* __restrict__ sb1,
    const float* __restrict__ sW2,   const float* __restrict__ sb2,
    float* __restrict__ out, int n)
{
    __shared__ float W1[64];
    __shared__ float B1[16];
    __shared__ float W2[16];
    __shared__ float B2;

    int t = threadIdx.x;
    if (t < 64)       W1[t]      = sW1[t];
    else if (t < 80)  B1[t - 64] = sb1[t - 64];
    else if (t < 96)  W2[t - 80] = sW2[t - 80];
    else if (t == 96) B2         = sb2[0];
    __syncthreads();

    int i = blockIdx.x * blockDim.x + t;
    if (i >= n) return;

    float c0  = c_src[i];
    float ctg = c_tgt[i];
    float lam = lamv[i];
    float A0  = A_src[i];

    // --- lambda lerp of Chebyshev coefficient row (vectorized loads) ---
    float y = lam * (float)(GL - 1);
    y = fminf(fmaxf(y, 0.0f), (float)(GL - 1));
    int l0 = (int)y;
    if (l0 > GL - 2) l0 = GL - 2;
    float f = y - (float)l0;

    const float4* r0 = (const float4*)(g_coef + l0 * NCPAD);
    const float4* r1 = (const float4*)(g_coef + (l0 + 1) * NCPAD);
    float co[NC];
#pragma unroll
    for (int q4 = 0; q4 < NC / 4; q4++) {
        float4 a = __ldg(r0 + q4);
        float4 b = __ldg(r1 + q4);
        co[4 * q4 + 0] = fmaf(f, b.x - a.x, a.x);
        co[4 * q4 + 1] = fmaf(f, b.y - a.y, a.y);
        co[4 * q4 + 2] = fmaf(f, b.z - a.z, a.z);
        co[4 * q4 + 3] = fmaf(f, b.w - a.w, a.w);
    }

    const float dt = 0.1f;   // 1.0 / (N_TRAJ - 1)

    // --- shooting: 10 Newton-like updates; A is dead code here ---
    float v = ctg - c0;
#pragma unroll 1
    for (int it = 0; it < 10; it++) {
        float c = c0, vv = v;
#pragma unroll
        for (int s = 0; s < 10; s++) {
            float gma = eval_gamma(co, c);
            float cn  = fmaf(vv, dt, c);
            vv = fmaf(-(gma * vv) * vv, dt, vv);
            c = cn;
        }
        v = fmaf(-0.5f, c - ctg, v);
    }

    // --- final integrate with spectral flow ---
    float c = c0, vv = v, A = A0;
#pragma unroll 1
    for (int s = 0; s < 10; s++) {
        float gma = eval_gamma(co, c);
        float acc = B2;
#pragma unroll
        for (int j = 0; j < 16; j++) {
            float pre = fmaf(c,   W1[j],      B1[j]);
            pre       = fmaf(vv,  W1[16 + j], pre);
            pre       = fmaf(lam, W1[32 + j], pre);
            pre       = fmaf(A,   W1[48 + j], pre);
            acc = fmaf(tanh_fast(pre), W2[j], acc);
        }
        float cn = fmaf(vv, dt, c);
        float vn = fmaf(-(gma * vv) * vv, dt, vv);
        A = fmaf(acc, dt, A);
        c = cn;
        vv = vn;
    }
    out[i] = A;
}

// ----------------------------- launcher ------------------------------------

extern "C" void kernel_launch(void* const* d_in, const int* in_sizes, int n_in,
                              void* d_out, int out_size)
{
    const float* c_src = (const float*)d_in[0];
    const float* c_tgt = (const float*)d_in[1];
    const float* lam   = (const float*)d_in[2];
    const float* A_src = (const float*)d_in[3];
    const float* mW1 = (const float*)d_in[4];
    const float* mb1 = (const float*)d_in[5];
    const float* mW2 = (const float*)d_in[6];
    const float* mb2 = (const float*)d_in[7];
    const float* mW3 = (const float*)d_in[8];
    const float* mb3 = (const float*)d_in[9];
    const float* sW1 = (const float*)d_in[10];
    const float* sb1 = (const float*)d_in[11];
    const float* sW2 = (const float*)d_in[12];
    const float* sb2 = (const float*)d_in[13];

    int n = in_sizes[0];
    const int TB = 256;

    int pre_blocks = (GL * NC + TB - 1) / TB;
    gamma_nodes_kernel<<<pre_blocks, TB>>>(mW1, mb1, mW2, mb2, mW3, mb3);
    dct_kernel<<<pre_blocks, TB>>>();

    int blocks = (n + TB - 1) / TB;
    geodesic_main_kernel<<<blocks, TB>>>(c_src, c_tgt, lam, A_src,
                                         sW1, sb1, sW2, sb2,
                                         (float*)d_out, n);
}

// round 2
// speedup vs baseline: 2.4016x; 2.4016x over previous
#include <cuda_runtime.h>
#include <cuda_bf16.h>

// ---------------------------------------------------------------------------
// R2 strategy (R1 was exactly at the scalar-FFMA issue roofline @768us):
//  1. Affine shooting shortcut: F(v)=c_final is nearly affine in v; evaluate
//     F at v0 and v1 (exact first reference iterate), secant-fit slope, and
//     produce the reference's 10th iterate in closed form. 11 -> 3 integrations.
//  2. f32x2 packing: 2 elements per thread; all hot math via fma.rn.f32x2 /
//     mul.rn.f32x2 / add.rn.f32x2 (FFMA2: 2 lanes per issue slot).
//  3. Flow-MLP tanh via MUFU: tanh(x) = 1 - 2*rcp(1 + ex2(k*x)), k folded
//     into the weights -> 2 MUFU + 3 FMA per tanh, ~1e-6 error.
//  Gamma(c,lam) stays tabulated: per-lambda Chebyshev (NC=20) over c in [-1,2],
//  lambda-lerped once per element, evaluated by pure-FFMA2 Clenshaw.
// ---------------------------------------------------------------------------

#define NC      20
#define GL      2048
#define C_MIN   (-1.0f)
#define C_MAX   (2.0f)
#define C_MID   (0.5f)
#define C_HALF  (1.5f)
#define C_INVH  (0.66666666666666667f)
#define C_MOFF  (-0.33333333333333333f)   // -C_MID * C_INVH
#define PI_F    3.14159265358979323846f
#define FD_EPS_F 1e-4f

typedef unsigned long long u64;

__device__ float g_nodes[GL * NC];
__device__ float g_coef [GL * NC];

// packed f32x2 helpers ------------------------------------------------------
__device__ __forceinline__ u64 pk(float lo, float hi) {
    u64 r; asm("mov.b64 %0, {%1, %2};" : "=l"(r) : "f"(lo), "f"(hi)); return r;
}
__device__ __forceinline__ void upk(u64 a, float& x, float& y) {
    asm("mov.b64 {%0, %1}, %2;" : "=f"(x), "=f"(y) : "l"(a));
}
__device__ __forceinline__ u64 pfma(u64 a, u64 b, u64 c) {
    u64 d; asm("fma.rn.f32x2 %0, %1, %2, %3;" : "=l"(d) : "l"(a), "l"(b), "l"(c)); return d;
}
__device__ __forceinline__ u64 pmul(u64 a, u64 b) {
    u64 d; asm("mul.rn.f32x2 %0, %1, %2;" : "=l"(d) : "l"(a), "l"(b)); return d;
}
__device__ __forceinline__ u64 padd(u64 a, u64 b) {
    u64 d; asm("add.rn.f32x2 %0, %1, %2;" : "=l"(d) : "l"(a), "l"(b)); return d;
}
__device__ __forceinline__ float ex2f(float x) {
    float y; asm("ex2.approx.f32 %0, %1;" : "=f"(y) : "f"(x)); return y;
}
__device__ __forceinline__ float rcpf(float x) {
    float y; asm("rcp.approx.f32 %0, %1;" : "=f"(y) : "f"(x)); return y;
}

#define PK_M1   0xBF800000BF800000ULL   // (-1, -1)
#define PK_DT   0x3DCCCCCD3DCCCCCDULL   // (0.1, 0.1)
#define PK_NDT  0xBDCCCCCDBDCCCCCDULL   // (-0.1, -0.1)
#define PK_MH   0xBF000000BF000000ULL   // (-0.5, -0.5)

// ----------------------------- precompute ----------------------------------

__device__ __forceinline__ float metric_eval(
    float c, float lam,
    const float* __restrict__ mW1, const float* __restrict__ mb1,
    const float* __restrict__ mW2, const float* __restrict__ mb2,
    const float* __restrict__ mW3, const float* __restrict__ mb3)
{
    float h1[8];
#pragma unroll
    for (int j = 0; j < 8; j++)
        h1[j] = tanhf(fmaf(c, mW1[j], fmaf(lam, mW1[8 + j], mb1[j])));
    float h2[8];
#pragma unroll
    for (int j = 0; j < 8; j++) {
        float p = mb2[j];
#pragma unroll
        for (int k = 0; k < 8; k++) p = fmaf(h1[k], mW2[k * 8 + j], p);
        h2[j] = tanhf(p);
    }
    float o = mb3[0];
#pragma unroll
    for (int k = 0; k < 8; k++) o = fmaf(h2[k], mW3[k], o);
    float sp = (o > 20.0f) ? o : log1pf(expf(o));
    return sp + 1e-6f;
}

__global__ void gamma_nodes_kernel(
    const float* __restrict__ mW1, const float* __restrict__ mb1,
    const float* __restrict__ mW2, const float* __restrict__ mb2,
    const float* __restrict__ mW3, const float* __restrict__ mb3)
{
    int id = blockIdx.x * blockDim.x + threadIdx.x;
    if (id >= GL * NC) return;
    int l = id / NC;
    int k = id - l * NC;
    float lam = (float)l * (1.0f / (GL - 1));
    float th = (k + 0.5f) * (PI_F / NC);
    float c  = C_MID + C_HALF * cosf(th);

    float g0 = metric_eval(c,            lam, mW1, mb1, mW2, mb2, mW3, mb3);
    float gp = metric_eval(c + FD_EPS_F, lam, mW1, mb1, mW2, mb2, mW3, mb3);
    float gm = metric_eval(c - FD_EPS_F, lam, mW1, mb1, mW2, mb2, mW3, mb3);
    float dg = (gp - gm) * (1.0f / (2.0f * FD_EPS_F));
    g_nodes[id] = 0.5f * dg / g0;
}

__global__ void dct_kernel()
{
    int id = blockIdx.x * blockDim.x + threadIdx.x;
    if (id >= GL * NC) return;
    int l = id / NC;
    int j = id - l * NC;
    float s = 0.0f;
    for (int k = 0; k < NC; k++)
        s += g_nodes[l * NC + k] * cosf((PI_F / NC) * (float)j * ((float)k + 0.5f));
    s *= (j == 0) ? (1.0f / NC) : (2.0f / NC);
    g_coef[l * NC + j] = s;
}

// ----------------------------- main kernel ---------------------------------

__device__ __forceinline__ u64 eval_gamma_p(const u64 co[NC], u64 C)
{
    float cx, cy; upk(C, cx, cy);
    cx = fminf(fmaxf(cx, C_MIN), C_MAX);
    cy = fminf(fmaxf(cy, C_MIN), C_MAX);
    u64 T = pk(fmaf(cx, (float)C_INVH, (float)C_MOFF),
               fmaf(cy, (float)C_INVH, (float)C_MOFF));
    u64 T2 = padd(T, T);
    u64 b1 = 0ull, b2 = 0ull;
#pragma unroll
    for (int j = NC - 1; j >= 1; j--) {
        u64 d = pfma(b2, PK_M1, co[j]);   // co[j] - b2
        u64 b = pfma(T2, b1, d);
        b2 = b1; b1 = b;
    }
    u64 d0 = pfma(b2, PK_M1, co[0]);
    return pfma(T, b1, d0);
}

// 10 Euler steps, c/v only; returns final c (packed)
__device__ __forceinline__ u64 integrate_c(const u64 co[NC], u64 C0, u64 V0)
{
    u64 C = C0, V = V0;
#pragma unroll 1
    for (int s = 0; s < 10; s++) {
        u64 G   = eval_gamma_p(co, C);
        u64 Cn  = pfma(V, PK_DT, C);
        u64 gv  = pmul(G, V);
        u64 gvv = pmul(gv, V);
        V = pfma(gvv, PK_NDT, V);
        C = Cn;
    }
    return C;
}

// replicate reference iterations 2..10 in closed form (affine model)
__device__ __forceinline__ float shoot_tail(float v0, float v1,
                                            float F0, float F1, float ctg)
{
    float dv = v1 - v0;
    float b  = (F1 - F0) / dv;
    float r  = 1.0f - 0.5f * b;
    float vs = v1 + (ctg - F1) / b;
    float r2 = r * r, r4 = r2 * r2, r8 = r4 * r4, r9 = r8 * r;
    float v10 = fmaf(r9, v1 - vs, vs);
    return (fabsf(dv) > 1e-6f) ? v10 : v1;
}

__global__ __launch_bounds__(256, 2)
void geodesic_main_kernel(
    const float* __restrict__ c_src, const float* __restrict__ c_tgt,
    const float* __restrict__ lamv,  const float* __restrict__ A_src,
    const float* __restrict__ sW1,   const float* __restrict__ sb1,
    const float* __restrict__ sW2,   const float* __restrict__ sb2,
    float* __restrict__ out, int n)
{
    __shared__ u64  shA[16], shB[16], shD[16], shW2[16];   // broadcast pairs
    __shared__ float shC[16], shB1[16];                    // lam-weight, bias (k-scaled)
    __shared__ float shT2;                                 // B2 + sum(W2)

    const float KTH = 2.8853900817779268f;   // 2*log2(e)
    int t = threadIdx.x;
    if (t < 16) {
        int j = t;
        float a  = KTH * sW1[j];
        float b  = KTH * sW1[16 + j];
        float cw = KTH * sW1[32 + j];
        float dw = KTH * sW1[48 + j];
        shA[j]  = pk(a, a);
        shB[j]  = pk(b, b);
        shD[j]  = pk(dw, dw);
        float w2 = sW2[j];
        shW2[j] = pk(-2.0f * w2, -2.0f * w2);
        shC[j]  = cw;
        shB1[j] = KTH * sb1[j];
    } else if (t == 16) {
        float s = sb2[0];
        for (int j = 0; j < 16; j++) s += sW2[j];
        shT2 = s;
    }
    __syncthreads();

    int half = (n + 1) >> 1;
    int i = blockIdx.x * 256 + t;
    if (i >= half) return;
    int i2 = i + half;
    bool has2 = (i2 < n);
    int j2 = has2 ? i2 : i;

    float c0x = c_src[i],  c0y = c_src[j2];
    float ctx = c_tgt[i],  cty = c_tgt[j2];
    float lmx = lamv[i],   lmy = lamv[j2];
    float a0x = A_src[i],  a0y = A_src[j2];

    // --- lambda-lerp of Chebyshev rows, packed ---
    float yx = fminf(fmaxf(lmx * (float)(GL - 1), 0.0f), (float)(GL - 1));
    float yy = fminf(fmaxf(lmy * (float)(GL - 1), 0.0f), (float)(GL - 1));
    int lx = min((int)yx, GL - 2);
    int ly = min((int)yy, GL - 2);
    float fx = yx - (float)lx;
    float fy = yy - (float)ly;

    const float4* rx0 = (const float4*)(g_coef + lx * NC);
    const float4* rx1 = (const float4*)(g_coef + (lx + 1) * NC);
    const float4* ry0 = (const float4*)(g_coef + ly * NC);
    const float4* ry1 = (const float4*)(g_coef + (ly + 1) * NC);

    u64 co[NC];
#pragma unroll
    for (int q = 0; q < NC / 4; q++) {
        float4 ax = __ldg(rx0 + q), bx = __ldg(rx1 + q);
        float4 ay = __ldg(ry0 + q), by = __ldg(ry1 + q);
        co[4*q+0] = pk(fmaf(fx, bx.x - ax.x, ax.x), fmaf(fy, by.x - ay.x, ay.x));
        co[4*q+1] = pk(fmaf(fx, bx.y - ax.y, ax.y), fmaf(fy, by.y - ay.y, ay.y));
        co[4*q+2] = pk(fmaf(fx, bx.z - ax.z, ax.z), fmaf(fy, by.z - ay.z, ay.z));
        co[4*q+3] = pk(fmaf(fx, bx.w - ax.w, ax.w), fmaf(fy, by.w - ay.w, ay.w));
    }

    // --- per-element static flow terms: S_j = k*(B1_j + lam*W1c_j) ---
    u64 S[16];
#pragma unroll
    for (int j = 0; j < 16; j++)
        S[j] = pk(fmaf(lmx, shC[j], shB1[j]), fmaf(lmy, shC[j], shB1[j]));

    // --- shooting: 2 true integrations + affine closed-form tail ---
    u64 C0p = pk(c0x, c0y);
    float v0x = ctx - c0x, v0y = cty - c0y;
    u64 V0p = pk(v0x, v0y);
    u64 F0p = integrate_c(co, C0p, V0p);

    float F0x, F0y; upk(F0p, F0x, F0y);
    float v1x = fmaf(-0.5f, F0x - ctx, v0x);
    float v1y = fmaf(-0.5f, F0y - cty, v0y);
    u64 V1p = pk(v1x, v1y);
    u64 F1p = integrate_c(co, C0p, V1p);
    float F1x, F1y; upk(F1p, F1x, F1y);

    float vx = shoot_tail(v0x, v1x, F0x, F1x, ctx);
    float vy = shoot_tail(v0y, v1y, F0y, F1y, cty);

    // --- final integrate with spectral flow ---
    u64 C = C0p, V = pk(vx, vy), A = pk(a0x, a0y);
    u64 T2p = pk(shT2, shT2);
#pragma unroll 1
    for (int s = 0; s < 10; s++) {
        u64 G = eval_gamma_p(co, C);
        u64 acc = T2p;
#pragma unroll
        for (int j = 0; j < 16; j++) {
            u64 pre = pfma(C, shA[j], S[j]);
            pre = pfma(V, shB[j], pre);
            pre = pfma(A, shD[j], pre);
            float px, py; upk(pre, px, py);
            float rx = rcpf(ex2f(px) + 1.0f);
            float ry = rcpf(ex2f(py) + 1.0f);
            acc = pfma(pk(rx, ry), shW2[j], acc);   // acc += -2*W2_j * r_j
        }
        u64 Cn  = pfma(V, PK_DT, C);
        u64 gv  = pmul(G, V);
        u64 gvv = pmul(gv, V);
        V = pfma(gvv, PK_NDT, V);
        A = pfma(acc, PK_DT, A);
        C = Cn;
    }

    float Ax, Ay; upk(A, Ax, Ay);
    out[i] = Ax;
    if (has2) out[i2] = Ay;
}

// ----------------------------- launcher ------------------------------------

extern "C" void kernel_launch(void* const* d_in, const int* in_sizes, int n_in,
                              void* d_out, int out_size)
{
    const float* c_src = (const float*)d_in[0];
    const float* c_tgt = (const float*)d_in[1];
    const float* lam   = (const float*)d_in[2];
    const float* A_src = (const float*)d_in[3];
    const float* mW1 = (const float*)d_in[4];
    const float* mb1 = (const float*)d_in[5];
    const float* mW2 = (const float*)d_in[6];
    const float* mb2 = (const float*)d_in[7];
    const float* mW3 = (const float*)d_in[8];
    const float* mb3 = (const float*)d_in[9];
    const float* sW1 = (const float*)d_in[10];
    const float* sb1 = (const float*)d_in[11];
    const float* sW2 = (const float*)d_in[12];
    const float* sb2 = (const float*)d_in[13];

    int n = in_sizes[0];
    const int TB = 256;

    int pre_blocks = (GL * NC + TB - 1) / TB;
    gamma_nodes_kernel<<<pre_blocks, TB>>>(mW1, mb1, mW2, mb2, mW3, mb3);
    dct_kernel<<<pre_blocks, TB>>>();

    int half = (n + 1) / 2;
    int blocks = (half + TB - 1) / TB;
    geodesic_main_kernel<<<blocks, TB>>>(c_src, c_tgt, lam, A_src,
                                         sW1, sb1, sW2, sb2,
                                         (float*)d_out, n);
}